// round 9
// baseline (speedup 1.0000x reference)
#include <cuda_runtime.h>
#include <cuda_bf16.h>
#include <cstdint>
#include <cstddef>

typedef unsigned long long u64;
typedef unsigned int u32;

#define NROWS  65536
#define LATENT 256
#define NNODES 256
#define TM     64
#define NT     256
#define EPSF   1.1920929e-7f
#define MARGIN 0.08f
#define CAP    2048

// ---- smem layout (byte offsets from 1KB-aligned base) ----
#define SA_OFF(s) ((s) * 40960)            // A stage: 64 rows x 128B bf16
#define SB_OFF(s) ((s) * 40960 + 8192)     // B stage: 256 rows x 128B bf16
#define T_E2RAW 81920
#define T_E2D   82944
#define T_Z2P   83968
#define T_Z2RAW 84992
#define T_Z2PP  85248
#define T_RQM   85504
#define T_RQS   86528
#define T_QTHR  87552
#define T_RQSI  87808
#define T_KEY   88064
#define T_BMU   88576
#define T_CNT   88832
#define T_TAB   88848
#define SMEM_BYTES (88848 + 3072 + 1024)

__device__ __align__(1024) unsigned char g_Bt[4][256 * 64 * 2];  // prebuilt bf16 E tiles
__device__ float g_e2[NNODES];

__device__ __forceinline__ u32 smaddr(const void* p) { return (u32)__cvta_generic_to_shared(p); }
__device__ __forceinline__ u32 toff(int row, int kbyte) {
    u32 o = (u32)(row * 128 + kbyte);
    return o ^ ((o >> 3) & 0x70);          // SW128
}
__device__ __forceinline__ void cp16(u32 dst, const void* src) {
    asm volatile("cp.async.cg.shared.global [%0], [%1], 16;" :: "r"(dst), "l"(src));
}
__device__ __forceinline__ void cp_commit() { asm volatile("cp.async.commit_group;" ::: "memory"); }
__device__ __forceinline__ void cp_wait0()  { asm volatile("cp.async.wait_group 0;" ::: "memory"); }
__device__ __forceinline__ void ldsm4(u32* r, u32 addr) {
    asm volatile("ldmatrix.sync.aligned.m8n8.x4.shared.b16 {%0,%1,%2,%3}, [%4];"
                 : "=r"(r[0]), "=r"(r[1]), "=r"(r[2]), "=r"(r[3]) : "r"(addr));
}
__device__ __forceinline__ void mma16816(float* d, const u32* a, u32 b0, u32 b1) {
    asm volatile("mma.sync.aligned.m16n8k16.row.col.f32.bf16.bf16.f32 "
                 "{%0,%1,%2,%3}, {%4,%5,%6,%7}, {%8,%9}, {%0,%1,%2,%3};"
                 : "+f"(d[0]), "+f"(d[1]), "+f"(d[2]), "+f"(d[3])
                 : "r"(a[0]), "r"(a[1]), "r"(a[2]), "r"(a[3]), "r"(b0), "r"(b1));
}
// f32x2 helpers
__device__ __forceinline__ u64 packf2(float lo, float hi) {
    u64 d; asm("mov.b64 %0, {%1, %2};" : "=l"(d) : "f"(lo), "f"(hi)); return d;
}
__device__ __forceinline__ void unpackf2(float& lo, float& hi, u64 v) {
    asm("mov.b64 {%0, %1}, %2;" : "=f"(lo), "=f"(hi) : "l"(v));
}
__device__ __forceinline__ u64 add2(u64 a, u64 b) {
    u64 d; asm("add.rn.f32x2 %0, %1, %2;" : "=l"(d) : "l"(a), "l"(b)); return d;
}
__device__ __forceinline__ u64 mul2(u64 a, u64 b) {
    u64 d; asm("mul.rn.f32x2 %0, %1, %2;" : "=l"(d) : "l"(a), "l"(b)); return d;
}
__device__ __forceinline__ u64 fma2(u64 a, u64 b, u64 c) {
    u64 d; asm("fma.rn.f32x2 %0, %1, %2, %3;" : "=l"(d) : "l"(a), "l"(b), "l"(c)); return d;
}

// ---------- prep: e2 + bf16 swizzled E tiles ----------
__global__ void prep_kernel(const float* __restrict__ E) {
    int tid = blockIdx.x * 256 + threadIdx.x;  // 8192 threads
    if (tid < NNODES) {
        const float4* er = (const float4*)(E + (size_t)tid * LATENT);
        float s = 0.f;
        #pragma unroll 8
        for (int i = 0; i < 64; i++) { float4 v = er[i]; s += v.x*v.x + v.y*v.y + v.z*v.z + v.w*v.w; }
        g_e2[tid] = s;
    }
    if (tid < 8192) {   // 4 chunks x 256 nodes x 8 kgroups
        int chunk = tid >> 11, node = (tid >> 3) & 255, kg = tid & 7;
        const float* src = E + (size_t)node * LATENT + chunk * 64 + kg * 8;
        __nv_bfloat16 h[8];
        #pragma unroll
        for (int i = 0; i < 8; i++) h[i] = __float2bfloat16(src[i]);
        *(uint4*)(g_Bt[chunk] + toff(node, kg * 16)) = *(uint4*)h;
    }
}

// ---------- main ----------
__global__ void __launch_bounds__(NT, 2)
som_main(const float* __restrict__ Z, const float* __restrict__ E,
         const int* __restrict__ Alpha, float* __restrict__ out)
{
    extern __shared__ char smraw[];
    char* SB = (char*)(((uintptr_t)smraw + 1023) & ~(uintptr_t)1023);
    float* e2raw = (float*)(SB + T_E2RAW);
    float* e2d   = (float*)(SB + T_E2D);
    float* z2p   = (float*)(SB + T_Z2P);
    float* z2raw = (float*)(SB + T_Z2RAW);
    float* z2pp  = (float*)(SB + T_Z2PP);
    float* rqm   = (float*)(SB + T_RQM);
    float* rqsum = (float*)(SB + T_RQS);
    float* qthr  = (float*)(SB + T_QTHR);
    float* rqs   = (float*)(SB + T_RQSI);
    u64*   keyA  = (u64*)(SB + T_KEY);
    int*   bmuS  = (int*)(SB + T_BMU);
    int*   cnt   = (int*)(SB + T_CNT);
    u64*   tab   = (u64*)(SB + T_TAB);
    u32*   list  = (u32*)SB;               // overlays stage mem post-GEMM

    const int t = threadIdx.x, wid = t >> 5, lane = t & 31;
    const int g = lane >> 2, qd = lane & 3;
    const int R0 = blockIdx.x * TM;
    const int wr = (wid >> 2) * 32, wc = (wid & 3) * 64;

    // alpha (robust)
    int ai = Alpha[0];
    float aa = (ai > 0 && ai < 1000000) ? (float)ai : __int_as_float(ai);
    const float inva = 1.0f / aa;
    const float coef = -(aa + 1.0f) * 0.5f;
    const bool fast = (aa == 10.0f);
    const u64 cm2 = packf2(-2.f * inva, -2.f * inva);

    if (t < NNODES) {
        float e = g_e2[t];
        e2raw[t] = e;
        e2d[t]   = e * inva;
    }
    if (t == 0) *cnt = 0;
    if (t < TM) keyA[t] = ~0ull;

    // ---- GEMM: D = Z_tile(64x256) x E^T, bf16 HMMA, 4 k-chunks of 64 ----
    float acc[2][8][4];
    #pragma unroll
    for (int mt = 0; mt < 2; mt++)
        #pragma unroll
        for (int j = 0; j < 8; j++)
            #pragma unroll
            for (int c = 0; c < 4; c++) acc[mt][j][c] = 0.f;

    const int arow = t >> 2, akp = t & 3;   // A build: 4 threads/row, 16 floats each
    float z2acc = 0.f;

    // prologue: chunk 0 -> stage 0
    {
        const float4* zsrc = (const float4*)(Z + (size_t)(R0 + arow) * LATENT + akp * 16);
        float v[16];
        #pragma unroll
        for (int i = 0; i < 4; i++) *(float4*)(v + 4 * i) = zsrc[i];
        __nv_bfloat16 h[16];
        #pragma unroll
        for (int i = 0; i < 16; i++) { z2acc = fmaf(v[i], v[i], z2acc); h[i] = __float2bfloat16(v[i]); }
        *(uint4*)(SB + SA_OFF(0) + toff(arow, akp * 32))      = ((uint4*)h)[0];
        *(uint4*)(SB + SA_OFF(0) + toff(arow, akp * 32 + 16)) = ((uint4*)h)[1];
        #pragma unroll
        for (int i = 0; i < 8; i++) {
            int o = (t + NT * i) * 16;
            cp16(smaddr(SB + SB_OFF(0) + o), g_Bt[0] + o);
        }
        cp_commit();
    }

    for (int c = 0; c < 4; c++) {
        const int s = c & 1;
        cp_wait0();
        __syncthreads();           // stage s ready; stage s^1 consumers (chunk c-1) done

        if (c < 3) {               // issue chunk c+1 into stage s^1
            const float4* zsrc = (const float4*)(Z + (size_t)(R0 + arow) * LATENT + (c + 1) * 64 + akp * 16);
            float v[16];
            #pragma unroll
            for (int i = 0; i < 4; i++) *(float4*)(v + 4 * i) = zsrc[i];
            __nv_bfloat16 h[16];
            #pragma unroll
            for (int i = 0; i < 16; i++) { z2acc = fmaf(v[i], v[i], z2acc); h[i] = __float2bfloat16(v[i]); }
            *(uint4*)(SB + SA_OFF(1 - s) + toff(arow, akp * 32))      = ((uint4*)h)[0];
            *(uint4*)(SB + SA_OFF(1 - s) + toff(arow, akp * 32 + 16)) = ((uint4*)h)[1];
            #pragma unroll
            for (int i = 0; i < 8; i++) {
                int o = (t + NT * i) * 16;
                cp16(smaddr(SB + SB_OFF(1 - s) + o), g_Bt[c + 1] + o);
            }
            cp_commit();
        }

        // compute chunk c
        const u32 sAa = smaddr(SB + SA_OFF(s));
        const u32 sBa = smaddr(SB + SB_OFF(s));
        const int la = lane & 15, kh = lane >> 4;
        #pragma unroll
        for (int ks = 0; ks < 4; ks++) {
            const int kb = ks * 32 + kh * 16;
            u32 af[2][4];
            ldsm4(af[0], sAa + toff(wr + la, kb));
            ldsm4(af[1], sAa + toff(wr + 16 + la, kb));
            u32 bf[4][4];
            #pragma unroll
            for (int p = 0; p < 4; p++)
                ldsm4(bf[p], sBa + toff(wc + p * 16 + la, kb));
            #pragma unroll
            for (int mt = 0; mt < 2; mt++)
                #pragma unroll
                for (int j = 0; j < 8; j++)
                    mma16816(acc[mt][j], af[mt], bf[j >> 1][j & 1], bf[j >> 1][(j & 1) + 2]);
        }
    }

    // ---- z2 finalize ----
    z2p[arow * 4 + akp] = z2acc;
    __syncthreads();
    if (t < TM) {
        float z = z2p[4 * t] + z2p[4 * t + 1] + z2p[4 * t + 2] + z2p[4 * t + 3];
        z2raw[t] = z;
        z2pp[t]  = fmaf(z, inva, 1.0f);
    }
    __syncthreads();

    // ---- q eval (rsqrt(p^11) fast path), per-row qmax + qsum ----
    u64 ed2[8];
    #pragma unroll
    for (int j = 0; j < 8; j++) ed2[j] = *(const u64*)(e2d + wc + j * 8 + 2 * qd);

    float qmaxr[4], qsumr[4];
    #pragma unroll
    for (int mt = 0; mt < 2; mt++) {
        #pragma unroll
        for (int hf = 0; hf < 2; hf++) {
            const int row = wr + mt * 16 + hf * 8 + g;
            const u64 zp = packf2(z2pp[row], z2pp[row]);
            u64 qs2 = 0ull;
            float qmax = 0.f;
            #pragma unroll
            for (int j = 0; j < 8; j++) {
                u64 a2 = packf2(acc[mt][j][2 * hf], acc[mt][j][2 * hf + 1]);
                u64 p  = fma2(a2, cm2, add2(zp, ed2[j]));   // p = 1 + d*inva
                float q0, q1;
                if (fast) {
                    u64 x2 = mul2(p, p);
                    u64 x4 = mul2(x2, x2);
                    u64 x8 = mul2(x4, x4);
                    u64 x11 = mul2(mul2(x8, x2), p);
                    float lo, hi; unpackf2(lo, hi, x11);
                    q0 = rsqrtf(lo); q1 = rsqrtf(hi);
                } else {
                    float lo, hi; unpackf2(lo, hi, p);
                    q0 = exp2f(coef * __log2f(lo));
                    q1 = exp2f(coef * __log2f(hi));
                }
                qs2 = add2(qs2, packf2(q0, q1));
                qmax = fmaxf(qmax, fmaxf(q0, q1));
                acc[mt][j][2 * hf] = q0;                    // stash raw q
                acc[mt][j][2 * hf + 1] = q1;
            }
            float slo, shi; unpackf2(slo, shi, qs2);
            qmaxr[mt * 2 + hf] = qmax;
            qsumr[mt * 2 + hf] = slo + shi;
        }
    }
    #pragma unroll
    for (int i = 0; i < 4; i++) {
        qmaxr[i] = fmaxf(qmaxr[i], __shfl_xor_sync(0xffffffffu, qmaxr[i], 1));
        qmaxr[i] = fmaxf(qmaxr[i], __shfl_xor_sync(0xffffffffu, qmaxr[i], 2));
        qsumr[i] += __shfl_xor_sync(0xffffffffu, qsumr[i], 1);
        qsumr[i] += __shfl_xor_sync(0xffffffffu, qsumr[i], 2);
    }
    if (qd == 0) {
        #pragma unroll
        for (int i = 0; i < 4; i++) {
            const int row = wr + (i >> 1) * 16 + (i & 1) * 8 + g;
            rqm[row * 4 + (wid & 3)]   = qmaxr[i];
            rqsum[row * 4 + (wid & 3)] = qsumr[i];
        }
    }
    __syncthreads();
    if (t < TM) {
        float qm = 0.f, s = 0.f;
        #pragma unroll
        for (int k = 0; k < 4; k++) { qm = fmaxf(qm, rqm[t * 4 + k]); s += rqsum[t * 4 + k]; }
        rqs[t] = 1.0f / s;
        float pmin = exp2f(__log2f(qm) / coef);
        float y = pmin + MARGIN * inva;
        float qt;
        if (fast) {
            float y2 = y * y, y4 = y2 * y2, y8 = y4 * y4;
            qt = rsqrtf(y8 * y2 * y);
        } else {
            qt = exp2f(coef * __log2f(y));
        }
        qthr[t] = qt;
    }
    __syncthreads();

    const size_t NBOFF  = (size_t)NROWS * 256;
    const size_t QOFF   = (size_t)NROWS * 1536;
    const size_t BMUOFF = (size_t)NROWS * 1792;

    // ---- q stores FIRST (start the DRAM burst early) ----
    #pragma unroll
    for (int mt = 0; mt < 2; mt++)
        #pragma unroll
        for (int hf = 0; hf < 2; hf++) {
            const int row = wr + mt * 16 + hf * 8 + g;
            const float rq = rqs[row];
            #pragma unroll
            for (int j = 0; j < 8; j++) {
                float2 qv;
                qv.x = fmaf(acc[mt][j][2 * hf],     rq, EPSF);
                qv.y = fmaf(acc[mt][j][2 * hf + 1], rq, EPSF);
                *(float2*)(out + QOFF + (size_t)(R0 + row) * NNODES + wc + j * 8 + 2 * qd) = qv;
            }
        }

    // ---- candidate collection (q >= qthr[row]) ----
    #pragma unroll
    for (int mt = 0; mt < 2; mt++)
        #pragma unroll
        for (int hf = 0; hf < 2; hf++) {
            const int row = wr + mt * 16 + hf * 8 + g;
            const float th = qthr[row];
            #pragma unroll
            for (int j = 0; j < 8; j++)
                #pragma unroll
                for (int u2 = 0; u2 < 2; u2++) {
                    if (acc[mt][j][2 * hf + u2] >= th) {
                        int idx = atomicAdd(cnt, 1);
                        if (idx < CAP)
                            list[idx] = ((u32)row << 8) | (u32)(wc + j * 8 + 2 * qd + u2);
                    }
                }
        }
    __syncthreads();

    // ---- exact fp32 refinement: one warp per candidate ----
    {
        const int n = min(*cnt, CAP);
        for (int e = wid; e < n; e += 8) {
            u32 ent = list[e];
            int row = ent >> 8, node = ent & 255;
            const float4* zr = (const float4*)(Z + (size_t)(R0 + row) * LATENT);
            const float4* er = (const float4*)(E + (size_t)node * LATENT);
            float4 za = zr[lane * 2], zb = zr[lane * 2 + 1];
            float4 ea = er[lane * 2], eb = er[lane * 2 + 1];
            float d = za.x*ea.x + za.y*ea.y + za.z*ea.z + za.w*ea.w
                    + zb.x*eb.x + zb.y*eb.y + zb.z*eb.z + zb.w*eb.w;
            #pragma unroll
            for (int o = 16; o > 0; o >>= 1) d += __shfl_down_sync(0xffffffffu, d, o);
            if (lane == 0) {
                float dex = fmaxf(z2raw[row] + e2raw[node] - 2.f * d, 0.f);
                u64 key = ((u64)__float_as_uint(dex) << 32) | (u64)node;
                atomicMin(&keyA[row], key);
            }
        }
    }
    __syncthreads();
    if (t < TM) {
        int b = (int)(keyA[t] & 0xffffffffu);
        bmuS[t] = b;
        out[BMUOFF + R0 + t] = (float)b;
    }
    __syncthreads();

    // ---- gather table: copy v -> (dst element offset << 8) | src node ----
    for (int v = t; v < TM * 6; v += NT) {
        int row2 = v / 6, s = v - row2 * 6;
        int b = bmuS[row2];
        int idx;
        if (s <= 1) {
            idx = b;
        } else {
            int k1 = b >> 4, k2 = b & 15;
            if      (s == 2) idx = (((k1 + 15) & 15) << 4) + k2;   // up
            else if (s == 3) idx = (((k1 + 1)  & 15) << 4) + k2;   // down
            else if (s == 4) idx = (k1 << 4) + ((k2 + 1)  & 15);   // right
            else             idx = (k1 << 4) + ((k2 + 15) & 15);   // left
        }
        u64 dstoff = (s == 0)
            ? (u64)(R0 + row2) * LATENT
            : (u64)NBOFF + ((u64)(R0 + row2) * 5 + (s - 1)) * LATENT;
        tab[v] = (dstoff << 8) | (u64)(u32)idx;
    }
    __syncthreads();

    // ---- flat coalesced copy: 384 copies x 64 float4 segs ----
    #pragma unroll 4
    for (int i = 0; i < (TM * 6 * 64) / NT; i++) {
        int v = i * NT + t;
        int copy = v >> 6, seg = v & 63;
        u64 pk = tab[copy];
        int idx = (int)(pk & 0xff);
        u64 dstoff = pk >> 8;
        float4 val = ((const float4*)(E + (size_t)idx * LATENT))[seg];
        ((float4*)(out + dstoff))[seg] = val;
    }
}

extern "C" void kernel_launch(void* const* d_in, const int* in_sizes, int n_in,
                              void* d_out, int out_size) {
    const float* Z = (const float*)d_in[0];
    const float* E = (const float*)d_in[1];
    const int*   A = (const int*)d_in[2];
    float* out = (float*)d_out;

    prep_kernel<<<32, 256>>>(E);
    cudaFuncSetAttribute(som_main, cudaFuncAttributeMaxDynamicSharedMemorySize, SMEM_BYTES);
    som_main<<<NROWS / TM, NT, SMEM_BYTES>>>(Z, E, A, out);
}